// round 1
// baseline (speedup 1.0000x reference)
#include <cuda_runtime.h>
#include <cuda_bf16.h>
#include <math.h>

// Problem constants (match reference)
#define NN      2000000
#define NBX     512
#define NBY     512
#define XL      0.0f
#define YL      0.0f
#define BSX     1.953125f   // 1000/512, exact in fp32
#define BSY     1.953125f
#define INV_UPC 10.0f       // 1 / UNIT_PIN_CAP

__global__ __launch_bounds__(256) void node_area_kernel(
    const float* __restrict__ pos,        // [2N]: x then y
    const float* __restrict__ nsx,        // [N]
    const float* __restrict__ nsy,        // [N]
    const float* __restrict__ umap,       // [NBX*NBY], row-major [bx][by]
    const int*   __restrict__ pw,         // [N]
    float*       __restrict__ out,        // [N]
    int n)
{
    int i = blockIdx.x * blockDim.x + threadIdx.x;
    if (i >= n) return;

    float x = __ldg(&pos[i]);
    float y = __ldg(&pos[n + i]);
    float w = __ldg(&nsx[i]);
    float h = __ldg(&nsy[i]);
    float hix = x + w;
    float hiy = y + h;

    // floor bin indices — use fp32 division to match JAX edge behavior
    int bx0 = (int)floorf(x / BSX);
    int by0 = (int)floorf(y / BSY);

    // Axis overlaps with the K=2 bins starting at the floor bin.
    // Bin positions use the UNCLIPPED index (as in reference).
    float blx0 = (float)bx0 * BSX;          // left edge of bin bx0
    float ox0 = fmaxf(fminf(hix, blx0 + BSX)        - fmaxf(x, blx0),        0.0f);
    float ox1 = fmaxf(fminf(hix, blx0 + 2.0f * BSX) - fmaxf(x, blx0 + BSX),  0.0f);

    float bly0 = (float)by0 * BSY;
    float oy0 = fmaxf(fminf(hiy, bly0 + BSY)        - fmaxf(y, bly0),        0.0f);
    float oy1 = fmaxf(fminf(hiy, bly0 + 2.0f * BSY) - fmaxf(y, bly0 + BSY),  0.0f);

    // Clipped indices for the map gather
    int bx0c = min(max(bx0,     0), NBX - 1);
    int bx1c = min(max(bx0 + 1, 0), NBX - 1);
    int by0c = min(max(by0,     0), NBY - 1);
    int by1c = min(max(by0 + 1, 0), NBY - 1);

    const float* row0 = umap + (size_t)bx0c * NBY;
    const float* row1 = umap + (size_t)bx1c * NBY;
    float u00 = __ldg(&row0[by0c]);
    float u01 = __ldg(&row0[by1c]);
    float u10 = __ldg(&row1[by0c]);
    float u11 = __ldg(&row1[by1c]);

    float area = ox0 * (oy0 * u00 + oy1 * u01)
               + ox1 * (oy0 * u10 + oy1 * u11);

    float p = (float)__ldg(&pw[i]);
    out[i] = area * p * INV_UPC / (w * h);
}

extern "C" void kernel_launch(void* const* d_in, const int* in_sizes, int n_in,
                              void* d_out, int out_size)
{
    const float* pos  = (const float*)d_in[0];
    const float* nsx  = (const float*)d_in[1];
    const float* nsy  = (const float*)d_in[2];
    const float* umap = (const float*)d_in[3];
    const int*   pw   = (const int*)d_in[4];
    float*       out  = (float*)d_out;

    int n = in_sizes[1];  // node_size_x has N elements
    int threads = 256;
    int blocks = (n + threads - 1) / threads;
    node_area_kernel<<<blocks, threads>>>(pos, nsx, nsy, umap, pw, out, n);
}